// round 8
// baseline (speedup 1.0000x reference)
#include <cuda_runtime.h>
#include <cstdint>

#define MARGIN 0.1f
#define NANF_U 0x7fffffffu

#define TI 1024   // i per block (NI * BI)
#define TJ 64     // j per block
#define BI 256    // threads
#define NI 4      // i rows per thread
#define RT (TI / TJ)   // band width in j-tiles per i-tile row = 16

// Cross-block state; last block resets g_done/g_cnt each launch (graph-safe).
__device__ float        g_part[4096];
__device__ int          g_cnt;
__device__ unsigned int g_done;

// c - x as FFMA with immediate multiplier (rt=1 on sm_103a vs FADD rt=2).
__device__ __forceinline__ float fnegadd(float x, float c) {
    float r;
    asm("fma.rn.f32 %0, %1, 0fBF800000, %2;" : "=f"(r) : "f"(x), "f"(c));
    return r;
}
// acc += v as FFMA-imm (rt=1).
__device__ __forceinline__ void facc(float& a, float v) {
    asm("fma.rn.f32 %0, %1, 0f3F800000, %0;" : "+f"(a) : "f"(v));
}
// s = sign(dt) * dp : copy dt's sign bit onto dp via one LOP3. NaN-preserving.
__device__ __forceinline__ float sign_mul(float dp, float dt) {
    return __uint_as_float(__float_as_uint(dp) ^
                           (__float_as_uint(dt) & 0x80000000u));
}

// Triangle-tiled sweep. Blocks enumerate (i-tile r, j-tile) with j-tile >= RT*r.
//  - band block  (j0 <  i0+TI): full rectangle, weight 1 (same-tile pairs hit
//    twice as (a,b),(b,a) -> weight 2; diagonal once)
//  - upper block (j0 >= i0+TI): weight 2
// Per evaluated slot accumulate x = min(sign(dt)*dp, MARGIN):
//  valid -> min(s,m); masked/OOB (p=NaN) -> m; unmasked diag -> 0.
// Then sum_hinge = m*(N*N - nv) - A,  count = nv*(nv-1).
__global__ void __launch_bounds__(BI, 4)
mrl_pair(const float* __restrict__ p,
         const float* __restrict__ t,
         const int* __restrict__ m,
         int B, int n64, float* __restrict__ out) {
    __shared__ float2 sj[TJ];          // {t_j, p_j(NaN-folded)}
    __shared__ float red_s[BI / 32];
    __shared__ int   red_c[BI / 32];
    __shared__ int   s_is_last;

    const int tid = threadIdx.x;
    const float NANF = __uint_as_float(NANF_U);

    // Decode linear block id -> (i-tile r, j-tile). Row r owns n64 - RT*r.
    int bid = blockIdx.x, r = 0, rowcnt;
    while (bid >= (rowcnt = n64 - RT * r)) { bid -= rowcnt; r++; }
    const int i0 = r * TI;
    const int j0 = (RT * r + bid) * TJ;
    const bool band = (j0 < i0 + TI);

    // Stage j tile.
    if (tid < TJ) {
        int j = j0 + tid;
        float tj = 0.f, pj = NANF;
        if (j < B) {
            tj = t[j];
            if (m[j] != 0) pj = p[j];
        }
        sj[tid] = make_float2(tj, pj);
    }
    __syncthreads();

    // i rows (NaN-folded). The j0==i0 block of each row counts mask bits.
    float ti[NI], pi[NI];
    int lcnt = 0;
#pragma unroll
    for (int q = 0; q < NI; q++) {
        int i = i0 + q * BI + tid;
        ti[q] = 0.f;
        pi[q] = NANF;
        if (i < B) {
            ti[q] = t[i];
            if (m[i] != 0) { pi[q] = p[i]; lcnt++; }
        }
    }
    if (j0 != i0) lcnt = 0;

    float acc[2 * NI];
#pragma unroll
    for (int k = 0; k < 2 * NI; k++) acc[k] = 0.f;

    const float4* sj4 = reinterpret_cast<const float4*>(sj);
#pragma unroll 4
    for (int k = 0; k < TJ / 2; k++) {
        float4 v = sj4[k];   // {t0, p0, t1, p1}
#pragma unroll
        for (int q = 0; q < NI; q++) {
            float dt0 = fnegadd(v.x, ti[q]);
            float dp0 = fnegadd(v.y, pi[q]);
            facc(acc[2 * q], fminf(sign_mul(dp0, dt0), MARGIN));
            float dt1 = fnegadd(v.z, ti[q]);
            float dp1 = fnegadd(v.w, pi[q]);
            facc(acc[2 * q + 1], fminf(sign_mul(dp1, dt1), MARGIN));
        }
    }

    float lsum = 0.f;
#pragma unroll
    for (int k = 0; k < 2 * NI; k++) lsum += acc[k];
    if (!band) lsum *= 2.0f;    // strictly-upper tiles stand for both orders

#pragma unroll
    for (int off = 16; off > 0; off >>= 1) {
        lsum += __shfl_down_sync(0xFFFFFFFFu, lsum, off);
        lcnt += __shfl_down_sync(0xFFFFFFFFu, lcnt, off);
    }
    const int wid = tid >> 5, lid = tid & 31;
    if (lid == 0) { red_s[wid] = lsum; red_c[wid] = lcnt; }
    __syncthreads();

    const int nparts = gridDim.x;
    if (wid == 0) {
        constexpr int NW = BI / 32;
        float bs = (lid < NW) ? red_s[lid] : 0.f;
        int   bc = (lid < NW) ? red_c[lid] : 0;
#pragma unroll
        for (int off = 16; off > 0; off >>= 1) {
            bs += __shfl_down_sync(0xFFFFFFFFu, bs, off);
            bc += __shfl_down_sync(0xFFFFFFFFu, bc, off);
        }
        if (lid == 0) {
            g_part[blockIdx.x] = bs;
            if (bc) atomicAdd(&g_cnt, bc);
            __threadfence();
            unsigned int d = atomicAdd(&g_done, 1u);
            s_is_last = (d == (unsigned)(nparts - 1));
        }
    }
    __syncthreads();

    // Last block: reduce partials, apply analytic corrections, reset state.
    if (s_is_last) {
        double s = 0.0;
        for (int k = tid; k < nparts; k += BI) s += (double)g_part[k];
#pragma unroll
        for (int off = 16; off > 0; off >>= 1)
            s += __shfl_down_sync(0xFFFFFFFFu, s, off);
        __shared__ double rds[BI / 32];
        if (lid == 0) rds[wid] = s;
        __syncthreads();
        if (wid == 0) {
            constexpr int NW = BI / 32;
            double bs = (lid < NW) ? rds[lid] : 0.0;
#pragma unroll
            for (int off = 16; off > 0; off >>= 1)
                bs += __shfl_down_sync(0xFFFFFFFFu, bs, off);
            if (lid == 0) {
                double nv = (double)g_cnt;
                double N  = (double)(n64 * TJ);       // padded square dimension
                double sum = (double)MARGIN * (N * N - nv) - bs;
                double cnt = nv * (nv - 1.0);
                if (cnt < 1.0) cnt = 1.0;
                out[0] = (float)(sum / cnt);
                g_done = 0u;   // reset for next graph replay
                g_cnt = 0;
            }
        }
    }
}

extern "C" void kernel_launch(void* const* d_in, const int* in_sizes, int n_in,
                              void* d_out, int out_size) {
    const float* p = (const float*)d_in[0];
    const float* t = (const float*)d_in[1];
    const int*   m = (const int*)d_in[2];
    float* out = (float*)d_out;
    const int B = in_sizes[0];

    const int nt  = (B + TI - 1) / TI;     // i tiles
    const int n64 = nt * RT;               // j tiles across padded width
    int nblocks = 0;
    for (int r = 0; r < nt; r++) nblocks += n64 - RT * r;

    mrl_pair<<<nblocks, BI>>>(p, t, m, B, n64, out);
}